// round 14
// baseline (speedup 1.0000x reference)
#include <cuda_runtime.h>
#include <cuda_fp16.h>
#include <cstdint>
#include <cstddef>

#define B_SZ 8
#define L_SZ 12288
#define F_SZ 512
#define NTHREADS 256
#define M_TILE 32
#define N_TILES_CTA 384   /* L / M_TILE */
#define KC 32             /* k elements per chunk (64B rows fp16, SW64) */

// fp16-rounded copy of the conv kernel weights (12.5MB static device scratch)
__device__ __half g_Khf[(size_t)F_SZ * L_SZ];

// ---------------- helpers ----------------
__device__ __forceinline__ uint32_t smem_u32(const void* p) {
    uint32_t a;
    asm("{ .reg .u64 t; cvta.to.shared.u64 t, %1; cvt.u32.u64 %0, t; }" : "=r"(a) : "l"(p));
    return a;
}
#define SWZ64(o) ((o) ^ (((o) >> 3) & 0x30))

#define CP16(dst, src) \
    asm volatile("cp.async.cg.shared.global [%0], [%1], 16;" :: "r"(dst), "l"(src))
#define CP_COMMIT() asm volatile("cp.async.commit_group;" ::: "memory")
#define CP_WAIT(N) asm volatile("cp.async.wait_group %0;" :: "n"(N) : "memory")

__device__ __forceinline__ void ldsm4(uint32_t* r, uint32_t addr) {
    asm volatile("ldmatrix.sync.aligned.m8n8.x4.shared.b16 {%0,%1,%2,%3}, [%4];"
                 : "=r"(r[0]), "=r"(r[1]), "=r"(r[2]), "=r"(r[3]) : "r"(addr));
}

__device__ __forceinline__ void mma16(float* c, const uint32_t* a, uint32_t b0, uint32_t b1) {
    asm volatile(
        "mma.sync.aligned.m16n8k16.row.col.f32.f16.f16.f32 "
        "{%0,%1,%2,%3}, {%4,%5,%6,%7}, {%8,%9}, {%0,%1,%2,%3};"
        : "+f"(c[0]), "+f"(c[1]), "+f"(c[2]), "+f"(c[3])
        : "r"(a[0]), "r"(a[1]), "r"(a[2]), "r"(a[3]), "r"(b0), "r"(b1));
}

// ---------------- preprocess: round K to fp16 (round-to-nearest) ----------------
__global__ void round_fp16_kernel(const float* __restrict__ K) {
    size_t i = (size_t)blockIdx.x * blockDim.x + threadIdx.x;
    if (i < (size_t)F_SZ * L_SZ) {
        g_Khf[i] = __float2half_rn(K[i]);
    }
}

// ---------------- SMEM layout (bytes from dynamic smem base) ----------------
#define OFF_BIAS    0u        /* 512*4  = 2048  */
#define OFF_W       2048u     /* 512*16 = 8192  -> 10240 */
#define OFF_XR      10240u    /* 12384 halfs = 24768 -> 35008 */
#define OFF_A       35840u    /* 2 * 2048  = 4096  -> 39936 (1024-aligned) */
#define OFF_B       39936u    /* 2 * 32768 = 65536 -> 105472 (1024-aligned) */
#define A_STRIDE    2048u
#define B_STRIDE    32768u
#define SMEM_TOTAL  105472u

// ---------------- main fused kernel (2 CTAs/SM) ----------------
__global__ void __launch_bounds__(NTHREADS, 2)
conv_fused_kernel(const int* __restrict__ example,
                  const float* __restrict__ bias,
                  const float* __restrict__ dense_w,
                  const float* __restrict__ dense_b,
                  float* __restrict__ out) {
    extern __shared__ char smem[];
    const uint32_t smem_base = smem_u32(smem);
    const int tid = threadIdx.x;
    const int wid = tid >> 5;
    const int lane = tid & 31;
    const int wn = wid;            // 0..7 (N position: 64 filters per warp)

    // LPT schedule: heavy tiles (large T0) first
    const int i_tile = (N_TILES_CTA - 1) - (int)(blockIdx.x >> 3);
    const int b = (int)(blockIdx.x & 7);
    const int T0 = i_tile * M_TILE;
    const int C = i_tile + 1;      // 32-wide j-chunks (j <= T0+31)

    // ---- stage bias, dense_w, and reversed-fp16 x into SMEM ----
    {
        float* bs = (float*)(smem + OFF_BIAS);
        for (int f = tid; f < F_SZ; f += NTHREADS) bs[f] = bias[f];
        float4* ws = (float4*)(smem + OFF_W);
        const float4* wg = (const float4*)dense_w;
        for (int f = tid; f < F_SZ; f += NTHREADS) ws[f] = wg[f];
        // xr[a] = fp16(x[T0+31-a]) for a<=T0+31, else 0  (a in [0, T0+95))
        __half* xr = (__half*)(smem + OFF_XR);
        const int* ex = example + (size_t)b * L_SZ;
        const int atop = T0 + 95;
        for (int a = tid; a < atop; a += NTHREADS) {
            int xi = T0 + 31 - a;
            float v = (xi >= 0) ? ((float)ex[xi] * 0.5f - 1.0f) : 0.0f;
            xr[a] = __float2half_rn(v);
        }
    }
    __syncthreads();

    const __half* xr = (const __half*)(smem + OFF_XR);

    // ---- ldmatrix lane offsets (SW64, XOR-composed; col bits < 64, no carry) ----
    // A frag mt=0: row = lane&15; static col = ((lane>>4)<<4). Boot frag mt=1: rows +16.
    uint32_t a_pre, a_boot;
    {
        uint32_t rowbase = (uint32_t)(lane & 15) * 64u;
        uint32_t swz = (rowbase >> 3) & 0x30u;
        uint32_t col = (uint32_t)((lane >> 4) << 4);
        a_pre = rowbase + (col ^ swz);
        uint32_t rb2 = rowbase + 16u * 64u;
        uint32_t swz2 = (rb2 >> 3) & 0x30u;
        a_boot = rb2 + (col ^ swz2);
    }
    // B frag (n16 group g): n = wn*64 + g*16 + (lane&7) + (((lane>>4)&1)<<3);
    // static col byte = ((lane>>3)&1)<<4
    uint32_t b_pre[4];
    #pragma unroll
    for (int g = 0; g < 4; g++) {
        uint32_t n = (uint32_t)(wn * 64 + g * 16 + (lane & 7) + (((lane >> 4) & 1) << 3));
        uint32_t rowbase = n * 64u;
        uint32_t swz = (rowbase >> 3) & 0x30u;
        uint32_t col = (uint32_t)(((lane >> 3) & 1) << 4);
        b_pre[g] = rowbase + (col ^ swz);
    }

    // A build: thread t -> row = t>>3 (0..31), k-cols (t&7)*4..+3
    const int arow = tid >> 3;
    const int acol = (tid & 7) * 4;

    // Hoisted B cp.async addressing: 8 quanta of 16B per thread per chunk
    uint32_t b_srcoff[8];   // byte offset into g_Khf (add J*2 per chunk)
    uint32_t b_dsw[8];      // swizzled SMEM offset within a B stage
    #pragma unroll
    for (int q = 0; q < 8; q++) {
        int linear = tid + q * NTHREADS;   // 0..2047
        int f = linear >> 2;
        int ch = linear & 3;
        b_srcoff[q] = (uint32_t)(f * (L_SZ * 2) + ch * 16);
        b_dsw[q] = SWZ64((uint32_t)(f * 64 + ch * 16));
    }
    const char* kbase = (const char*)g_Khf;

    float acc[2][8][4];
    #pragma unroll
    for (int mt = 0; mt < 2; mt++)
        #pragma unroll
        for (int nt = 0; nt < 8; nt++)
            #pragma unroll
            for (int k = 0; k < 4; k++) acc[mt][nt][k] = 0.0f;

    // ---- chunk builder ----
    auto build_chunk = [&](int j, int st) {
        const int J = j * KC;
        // B: K[0:512, J:J+32] fp16, SW64
        #pragma unroll
        for (int q = 0; q < 8; q++) {
            const char* src = kbase + b_srcoff[q] + (uint32_t)(J * 2);
            uint32_t dst = smem_base + OFF_B + (uint32_t)st * B_STRIDE + b_dsw[q];
            CP16(dst, src);
        }
        // A: A[r,k] = x[T0+r-J-k] = xr[J+31-r+k]  (contiguous ascending in k)
        {
            char* Ab = smem + OFF_A + st * A_STRIDE;
            int a0 = J + 31 - arow + acol;
            __half2 p0 = __halves2half2(xr[a0], xr[a0 + 1]);
            __half2 p1 = __halves2half2(xr[a0 + 2], xr[a0 + 3]);
            uint2 v;
            v.x = *(const uint32_t*)&p0;
            v.y = *(const uint32_t*)&p1;
            uint32_t o = (uint32_t)(arow * 64 + acol * 2);
            *(uint2*)(Ab + SWZ64(o)) = v;
        }
        CP_COMMIT();
    };

    // ---- prologue ----
    build_chunk(0, 0);

    uint32_t prev[4];   // Toeplitz A chain: frag(mt=1, kk) == frag(mt=0, kk-1)

    // ---- mainloop: 2-stage ring, one barrier per chunk, build-after-barrier ----
    for (int c = 0; c < C; c++) {
        const int st = c & 1;
        CP_WAIT(0);                 // chunk c's group (issued last iter) done
        __syncthreads();            // B[c]/A[c] visible; stage st^1 reads all done
        if (c + 1 < C) build_chunk(c + 1, st ^ 1);

        const uint32_t abase = smem_base + OFF_A + (uint32_t)st * A_STRIDE;
        const uint32_t bbase = smem_base + OFF_B + (uint32_t)st * B_STRIDE;

        if (c == 0) ldsm4(prev, abase + a_boot);   // bootstrap frag(1,0)

        #pragma unroll
        for (int kk = 0; kk < 2; kk++) {           // 2 x k16 = 32 k per chunk
            const uint32_t kx = (uint32_t)(kk * 32);
            uint32_t cur[4];
            ldsm4(cur, abase + (a_pre ^ kx));      // frag(0,kk) -> also frag(1,kk+1)
            uint32_t bfr[4][4];
            #pragma unroll
            for (int g = 0; g < 4; g++)
                ldsm4(bfr[g], bbase + (b_pre[g] ^ kx));
            #pragma unroll
            for (int nt = 0; nt < 8; nt++) {
                mma16(acc[0][nt], cur,  bfr[nt >> 1][(nt & 1) * 2],
                      bfr[nt >> 1][(nt & 1) * 2 + 1]);
                mma16(acc[1][nt], prev, bfr[nt >> 1][(nt & 1) * 2],
                      bfr[nt >> 1][(nt & 1) * 2 + 1]);
            }
            #pragma unroll
            for (int r = 0; r < 4; r++) prev[r] = cur[r];
        }
    }
    __syncthreads();   // all stage reads done before epilogue reuses OFF_A

    // ---- fused epilogue: bias + ReLU + dense[512x4] ----
    {
        const float* bs = (const float*)(smem + OFF_BIAS);
        const float4* ws = (const float4*)(smem + OFF_W);
        const int g = lane >> 2;
        const int cp = lane & 3;

        // rows mt*16 + h*8 + g
        float4 part[2][2];
        #pragma unroll
        for (int mt = 0; mt < 2; mt++)
            #pragma unroll
            for (int h = 0; h < 2; h++) {
                float4 p = make_float4(0.f, 0.f, 0.f, 0.f);
                #pragma unroll
                for (int nt = 0; nt < 8; nt++) {
                    int f0 = wn * 64 + nt * 8 + 2 * cp;
                    float v0 = fmaxf(acc[mt][nt][h * 2 + 0] + bs[f0], 0.0f);
                    float v1 = fmaxf(acc[mt][nt][h * 2 + 1] + bs[f0 + 1], 0.0f);
                    float4 w0 = ws[f0];
                    float4 w1 = ws[f0 + 1];
                    p.x += v0 * w0.x + v1 * w1.x;
                    p.y += v0 * w0.y + v1 * w1.y;
                    p.z += v0 * w0.z + v1 * w1.z;
                    p.w += v0 * w0.w + v1 * w1.w;
                }
                part[mt][h] = p;
            }
        #pragma unroll
        for (int mt = 0; mt < 2; mt++)
            #pragma unroll
            for (int h = 0; h < 2; h++) {
                #pragma unroll
                for (int d = 1; d < 4; d <<= 1) {
                    part[mt][h].x += __shfl_xor_sync(0xFFFFFFFF, part[mt][h].x, d);
                    part[mt][h].y += __shfl_xor_sync(0xFFFFFFFF, part[mt][h].y, d);
                    part[mt][h].z += __shfl_xor_sync(0xFFFFFFFF, part[mt][h].z, d);
                    part[mt][h].w += __shfl_xor_sync(0xFFFFFFFF, part[mt][h].w, d);
                }
            }
        float4* P = (float4*)(smem + OFF_A);   // [32 rows][8 wn] = 4KB scratch
        if (cp == 0) {
            #pragma unroll
            for (int mt = 0; mt < 2; mt++)
                #pragma unroll
                for (int h = 0; h < 2; h++) {
                    int row = mt * 16 + h * 8 + g;
                    P[row * 8 + wn] = part[mt][h];
                }
        }
        __syncthreads();

        if (tid < M_TILE) {
            float4 db = *(const float4*)dense_b;
            float4 o = db;
            #pragma unroll
            for (int w = 0; w < 8; w++) {
                float4 p = P[tid * 8 + w];
                o.x += p.x; o.y += p.y; o.z += p.z; o.w += p.w;
            }
            ((float4*)out)[(size_t)b * L_SZ + T0 + tid] = o;
        }
    }
}

extern "C" void kernel_launch(void* const* d_in, const int* in_sizes, int n_in,
                              void* d_out, int out_size) {
    const int*   example = (const int*)d_in[0];
    const float* kern    = (const float*)d_in[1];
    const float* bias    = (const float*)d_in[2];
    const float* dense_w = (const float*)d_in[3];
    const float* dense_b = (const float*)d_in[4];
    float* out = (float*)d_out;

    cudaFuncSetAttribute(conv_fused_kernel,
                         cudaFuncAttributeMaxDynamicSharedMemorySize, SMEM_TOTAL);

    // 1) round conv weights to fp16-RN into static scratch
    {
        size_t n = (size_t)F_SZ * L_SZ;
        int blocks = (int)((n + 255) / 256);
        round_fp16_kernel<<<blocks, 256>>>(kern);
    }
    // 2) fused Toeplitz-GEMM + bias + ReLU + dense  (2 CTAs per SM)
    conv_fused_kernel<<<B_SZ * N_TILES_CTA, NTHREADS, SMEM_TOTAL>>>(
        example, bias, dense_w, dense_b, out);
}

// round 15
// speedup vs baseline: 1.1233x; 1.1233x over previous
#include <cuda_runtime.h>
#include <cuda_fp16.h>
#include <cstdint>
#include <cstddef>

#define B_SZ 8
#define L_SZ 12288
#define F_SZ 512
#define NTHREADS 256
#define M_TILE 64
#define N_CTA 256          /* filters per CTA (split across 2 CTAs) */
#define N_TILES 192        /* L / M_TILE */
#define KC 32              /* k elements per chunk (64B rows fp16, SW64) */

// fp16-rounded copy of the conv kernel weights (12.5MB static device scratch)
__device__ __half g_Khf[(size_t)F_SZ * L_SZ];

// ---------------- helpers ----------------
__device__ __forceinline__ uint32_t smem_u32(const void* p) {
    uint32_t a;
    asm("{ .reg .u64 t; cvta.to.shared.u64 t, %1; cvt.u32.u64 %0, t; }" : "=r"(a) : "l"(p));
    return a;
}
#define SWZ64(o) ((o) ^ (((o) >> 3) & 0x30))

#define CP16(dst, src) \
    asm volatile("cp.async.cg.shared.global [%0], [%1], 16;" :: "r"(dst), "l"(src))
#define CP_COMMIT() asm volatile("cp.async.commit_group;" ::: "memory")
#define CP_WAIT(N) asm volatile("cp.async.wait_group %0;" :: "n"(N) : "memory")

__device__ __forceinline__ void ldsm4(uint32_t* r, uint32_t addr) {
    asm volatile("ldmatrix.sync.aligned.m8n8.x4.shared.b16 {%0,%1,%2,%3}, [%4];"
                 : "=r"(r[0]), "=r"(r[1]), "=r"(r[2]), "=r"(r[3]) : "r"(addr));
}

__device__ __forceinline__ void mma16(float* c, const uint32_t* a, uint32_t b0, uint32_t b1) {
    asm volatile(
        "mma.sync.aligned.m16n8k16.row.col.f32.f16.f16.f32 "
        "{%0,%1,%2,%3}, {%4,%5,%6,%7}, {%8,%9}, {%0,%1,%2,%3};"
        : "+f"(c[0]), "+f"(c[1]), "+f"(c[2]), "+f"(c[3])
        : "r"(a[0]), "r"(a[1]), "r"(a[2]), "r"(a[3]), "r"(b0), "r"(b1));
}

// ---------------- preprocess kernels ----------------
__global__ void round_fp16_kernel(const float* __restrict__ K) {
    size_t i = (size_t)blockIdx.x * blockDim.x + threadIdx.x;
    if (i < (size_t)F_SZ * L_SZ) {
        g_Khf[i] = __float2half_rn(K[i]);
    }
}

__global__ void zero_out_kernel(float4* __restrict__ out) {
    // 8*12288*4 floats = 98304 float4
    out[blockIdx.x * 256 + threadIdx.x] = make_float4(0.f, 0.f, 0.f, 0.f);
}

// ---------------- SMEM layout (bytes from dynamic smem base) ----------------
#define OFF_BIAS    0u        /* 256*4  = 1024  */
#define OFF_W       1024u     /* 256*16 = 4096  -> 5120  */
#define OFF_XR      5120u     /* (12288+128) halfs = 24832 -> 29952 */
#define OFF_A       30720u    /* 3 * 4096  = 12288 -> 43008 (1024-aligned) */
#define OFF_B       43008u    /* 3 * 16384 = 49152 -> 92160 (1024-aligned) */
#define A_STRIDE    4096u
#define B_STRIDE    16384u
#define SMEM_TOTAL  92160u

// ---------------- main fused kernel (2 CTAs/SM, N-split) ----------------
__global__ void __launch_bounds__(NTHREADS, 2)
conv_fused_kernel(const int* __restrict__ example,
                  const float* __restrict__ bias,
                  const float* __restrict__ dense_w,
                  const float* __restrict__ dense_b,
                  float* __restrict__ out) {
    extern __shared__ char smem[];
    const uint32_t smem_base = smem_u32(smem);
    const int tid = threadIdx.x;
    const int wid = tid >> 5;
    const int lane = tid & 31;
    const int wm = wid >> 2;       // 0..1 (M: 32 rows per warp)
    const int wn = wid & 3;        // 0..3 (N: 64 filters per warp, of this CTA's 256)

    // grid: 192 tiles x 8 batches x 2 filter-halves; LPT (heavy tiles first)
    const int bx = (int)blockIdx.x;
    const int i_tile = (N_TILES - 1) - (bx >> 4);
    const int b = (bx >> 1) & 7;
    const int nb = bx & 1;
    const int T0 = i_tile * M_TILE;
    const int C = (T0 >> 5) + 2;   // 32-wide j-chunks (j <= T0+63)
    const int fbase = nb * N_CTA;

    // ---- stage bias, dense_w (this CTA's 256 filters), reversed-fp16 x ----
    {
        float* bs = (float*)(smem + OFF_BIAS);
        for (int f = tid; f < N_CTA; f += NTHREADS) bs[f] = bias[fbase + f];
        float4* ws = (float4*)(smem + OFF_W);
        const float4* wg = (const float4*)dense_w;
        for (int f = tid; f < N_CTA; f += NTHREADS) ws[f] = wg[fbase + f];
        // xr[a] = fp16(x[T0+63-a]) for a<=T0+63, else 0  (a in [0, T0+128))
        __half* xr = (__half*)(smem + OFF_XR);
        const int* ex = example + (size_t)b * L_SZ;
        const int atop = T0 + 128;
        for (int a = tid; a < atop; a += NTHREADS) {
            int xi = T0 + 63 - a;
            float v = (xi >= 0) ? ((float)ex[xi] * 0.5f - 1.0f) : 0.0f;
            xr[a] = __float2half_rn(v);
        }
    }
    __syncthreads();

    const __half* xr = (const __half*)(smem + OFF_XR);

    // ---- ldmatrix lane offsets (SW64, XOR-composed; col bits < 64, no carry) ----
    // A frag mt=0: row = wm*32 + (lane&15); static col = ((lane>>4)<<4). Boot mt=1: +16 rows.
    uint32_t a_pre, a_boot;
    {
        uint32_t rowbase = (uint32_t)(wm * 32 + (lane & 15)) * 64u;
        uint32_t swz = (rowbase >> 3) & 0x30u;
        uint32_t col = (uint32_t)((lane >> 4) << 4);
        a_pre = rowbase + (col ^ swz);
        uint32_t rb2 = rowbase + 16u * 64u;
        uint32_t swz2 = (rb2 >> 3) & 0x30u;
        a_boot = rb2 + (col ^ swz2);
    }
    // B frag (n16 group g): n = wn*64 + g*16 + (lane&7) + (((lane>>4)&1)<<3);
    // static col byte = ((lane>>3)&1)<<4
    uint32_t b_pre[4];
    #pragma unroll
    for (int g = 0; g < 4; g++) {
        uint32_t n = (uint32_t)(wn * 64 + g * 16 + (lane & 7) + (((lane >> 4) & 1) << 3));
        uint32_t rowbase = n * 64u;
        uint32_t swz = (rowbase >> 3) & 0x30u;
        uint32_t col = (uint32_t)(((lane >> 3) & 1) << 4);
        b_pre[g] = rowbase + (col ^ swz);
    }

    // A build: thread t -> row = t>>2 (0..63), k-cols (t&3)*8 .. +7 (16B fp16)
    const int arow = tid >> 2;
    const int acol = (tid & 3) * 8;

    // Hoisted B cp.async addressing: 4 quanta of 16B per thread per chunk
    uint32_t b_srcoff[4];   // byte offset into g_Khf (add J*2 per chunk)
    uint32_t b_dsw[4];      // swizzled SMEM offset within a B stage
    #pragma unroll
    for (int q = 0; q < 4; q++) {
        int linear = tid + q * NTHREADS;   // 0..1023
        int f = linear >> 2;               // 0..255 local filter
        int ch = linear & 3;
        b_srcoff[q] = (uint32_t)((fbase + f) * (L_SZ * 2) + ch * 16);
        b_dsw[q] = SWZ64((uint32_t)(f * 64 + ch * 16));
    }
    const char* kbase = (const char*)g_Khf;

    float acc[2][8][4];
    #pragma unroll
    for (int mt = 0; mt < 2; mt++)
        #pragma unroll
        for (int nt = 0; nt < 8; nt++)
            #pragma unroll
            for (int k = 0; k < 4; k++) acc[mt][nt][k] = 0.0f;

    // ---- chunk builder ----
    auto build_chunk = [&](int j, int st) {
        const int J = j * KC;
        #pragma unroll
        for (int q = 0; q < 4; q++) {
            const char* src = kbase + b_srcoff[q] + (uint32_t)(J * 2);
            uint32_t dst = smem_base + OFF_B + (uint32_t)st * B_STRIDE + b_dsw[q];
            CP16(dst, src);
        }
        // A[r,k] = x[T0+r-J-k] = xr[J+63-r+k] (contiguous ascending in k)
        {
            char* Ab = smem + OFF_A + st * A_STRIDE;
            int a0 = J + 63 - arow + acol;
            __half2 p0 = __halves2half2(xr[a0],     xr[a0 + 1]);
            __half2 p1 = __halves2half2(xr[a0 + 2], xr[a0 + 3]);
            __half2 p2 = __halves2half2(xr[a0 + 4], xr[a0 + 5]);
            __half2 p3 = __halves2half2(xr[a0 + 6], xr[a0 + 7]);
            uint4 v;
            v.x = *(const uint32_t*)&p0;
            v.y = *(const uint32_t*)&p1;
            v.z = *(const uint32_t*)&p2;
            v.w = *(const uint32_t*)&p3;
            uint32_t o = (uint32_t)(arow * 64 + acol * 2);
            *(uint4*)(Ab + SWZ64(o)) = v;
        }
        CP_COMMIT();
    };

    // ---- prologue: chunks 0 and 1 ----
    build_chunk(0, 0);
    if (C > 1) build_chunk(1, 1);

    uint32_t prev[4];   // Toeplitz A chain: frag(mt=1, kk) == frag(mt=0, kk-1)

    // ---- mainloop: 3-stage ring, depth-2 prefetch, one barrier per chunk ----
    for (int c = 0; c < C; c++) {
        const int st = c - (c / 3) * 3;   // c % 3
        if (c + 1 < C) { CP_WAIT(1); }    // group c done; c+1 may be in flight
        else           { CP_WAIT(0); }
        __syncthreads();                  // stage c visible; stage (c+2)%3 reads done
        if (c + 2 < C) build_chunk(c + 2, (c + 2) % 3);

        const uint32_t abase = smem_base + OFF_A + (uint32_t)st * A_STRIDE;
        const uint32_t bbase = smem_base + OFF_B + (uint32_t)st * B_STRIDE;

        if (c == 0) ldsm4(prev, abase + a_boot);   // bootstrap frag(1,0)

        #pragma unroll
        for (int kk = 0; kk < 2; kk++) {           // 2 x k16 = 32 k per chunk
            const uint32_t kx = (uint32_t)(kk * 32);
            uint32_t cur[4];
            ldsm4(cur, abase + (a_pre ^ kx));      // frag(0,kk) -> also frag(1,kk+1)
            uint32_t bfr[4][4];
            #pragma unroll
            for (int g = 0; g < 4; g++)
                ldsm4(bfr[g], bbase + (b_pre[g] ^ kx));
            #pragma unroll
            for (int nt = 0; nt < 8; nt++) {
                mma16(acc[0][nt], cur,  bfr[nt >> 1][(nt & 1) * 2],
                      bfr[nt >> 1][(nt & 1) * 2 + 1]);
                mma16(acc[1][nt], prev, bfr[nt >> 1][(nt & 1) * 2],
                      bfr[nt >> 1][(nt & 1) * 2 + 1]);
            }
            #pragma unroll
            for (int r = 0; r < 4; r++) prev[r] = cur[r];
        }
    }
    __syncthreads();   // all stage reads done before epilogue reuses OFF_A

    // ---- fused epilogue: bias + ReLU + dense[256x4] partial, atomicAdd ----
    {
        const float* bs = (const float*)(smem + OFF_BIAS);
        const float4* ws = (const float4*)(smem + OFF_W);
        const int g = lane >> 2;
        const int cp = lane & 3;

        // rows wm*32 + mt*16 + h*8 + g
        float4 part[2][2];
        #pragma unroll
        for (int mt = 0; mt < 2; mt++)
            #pragma unroll
            for (int h = 0; h < 2; h++) {
                float4 p = make_float4(0.f, 0.f, 0.f, 0.f);
                #pragma unroll
                for (int nt = 0; nt < 8; nt++) {
                    int f0 = wn * 64 + nt * 8 + 2 * cp;    // local filter
                    float v0 = fmaxf(acc[mt][nt][h * 2 + 0] + bs[f0], 0.0f);
                    float v1 = fmaxf(acc[mt][nt][h * 2 + 1] + bs[f0 + 1], 0.0f);
                    float4 w0 = ws[f0];
                    float4 w1 = ws[f0 + 1];
                    p.x += v0 * w0.x + v1 * w1.x;
                    p.y += v0 * w0.y + v1 * w1.y;
                    p.z += v0 * w0.z + v1 * w1.z;
                    p.w += v0 * w0.w + v1 * w1.w;
                }
                part[mt][h] = p;
            }
        #pragma unroll
        for (int mt = 0; mt < 2; mt++)
            #pragma unroll
            for (int h = 0; h < 2; h++) {
                #pragma unroll
                for (int d = 1; d < 4; d <<= 1) {
                    part[mt][h].x += __shfl_xor_sync(0xFFFFFFFF, part[mt][h].x, d);
                    part[mt][h].y += __shfl_xor_sync(0xFFFFFFFF, part[mt][h].y, d);
                    part[mt][h].z += __shfl_xor_sync(0xFFFFFFFF, part[mt][h].z, d);
                    part[mt][h].w += __shfl_xor_sync(0xFFFFFFFF, part[mt][h].w, d);
                }
            }
        float4* P = (float4*)(smem + OFF_A);   // [64 rows][4 wn] = 4KB scratch
        if (cp == 0) {
            #pragma unroll
            for (int mt = 0; mt < 2; mt++)
                #pragma unroll
                for (int h = 0; h < 2; h++) {
                    int row = wm * 32 + mt * 16 + h * 8 + g;
                    P[row * 4 + wn] = part[mt][h];
                }
        }
        __syncthreads();

        if (tid < M_TILE) {
            float4 o = make_float4(0.f, 0.f, 0.f, 0.f);
            #pragma unroll
            for (int w = 0; w < 4; w++) {
                float4 p = P[tid * 4 + w];
                o.x += p.x; o.y += p.y; o.z += p.z; o.w += p.w;
            }
            if (nb == 0) {
                float4 db = *(const float4*)dense_b;
                o.x += db.x; o.y += db.y; o.z += db.z; o.w += db.w;
            }
            float* dst = out + ((size_t)b * L_SZ + T0 + tid) * 4;
            atomicAdd(dst + 0, o.x);
            atomicAdd(dst + 1, o.y);
            atomicAdd(dst + 2, o.z);
            atomicAdd(dst + 3, o.w);
        }
    }
}

extern "C" void kernel_launch(void* const* d_in, const int* in_sizes, int n_in,
                              void* d_out, int out_size) {
    const int*   example = (const int*)d_in[0];
    const float* kern    = (const float*)d_in[1];
    const float* bias    = (const float*)d_in[2];
    const float* dense_w = (const float*)d_in[3];
    const float* dense_b = (const float*)d_in[4];
    float* out = (float*)d_out;

    cudaFuncSetAttribute(conv_fused_kernel,
                         cudaFuncAttributeMaxDynamicSharedMemorySize, SMEM_TOTAL);

    // 1) zero the output (filter-split CTAs accumulate via atomicAdd)
    zero_out_kernel<<<384, 256>>>((float4*)out);
    // 2) round conv weights to fp16-RN into static scratch
    {
        size_t n = (size_t)F_SZ * L_SZ;
        int blocks = (int)((n + 255) / 256);
        round_fp16_kernel<<<blocks, 256>>>(kern);
    }
    // 3) fused Toeplitz-GEMM + bias + ReLU + dense, N-split, 2 CTAs/SM
    conv_fused_kernel<<<N_TILES * B_SZ * 2, NTHREADS, SMEM_TOTAL>>>(
        example, bias, dense_w, dense_b, out);
}

// round 16
// speedup vs baseline: 1.2327x; 1.0974x over previous
#include <cuda_runtime.h>
#include <cuda_fp16.h>
#include <cstdint>
#include <cstddef>

#define B_SZ 8
#define L_SZ 12288
#define F_SZ 512
#define NTHREADS 256
#define M_TILE 64
#define N_CTA 256          /* filters per CTA (split across 2 CTAs) */
#define N_TILES 192        /* L / M_TILE */
#define KC 64              /* k elements per chunk (128B rows fp16, SW128) */

// fp16-rounded copy of the conv kernel weights (12.5MB static device scratch)
__device__ __half g_Khf[(size_t)F_SZ * L_SZ];

// ---------------- helpers ----------------
__device__ __forceinline__ uint32_t smem_u32(const void* p) {
    uint32_t a;
    asm("{ .reg .u64 t; cvta.to.shared.u64 t, %1; cvt.u32.u64 %0, t; }" : "=r"(a) : "l"(p));
    return a;
}
#define SWZ128(o) ((o) ^ (((o) >> 3) & 0x70))

#define CP16(dst, src) \
    asm volatile("cp.async.cg.shared.global [%0], [%1], 16;" :: "r"(dst), "l"(src))
#define CP_COMMIT() asm volatile("cp.async.commit_group;" ::: "memory")
#define CP_WAIT(N) asm volatile("cp.async.wait_group %0;" :: "n"(N) : "memory")

__device__ __forceinline__ void ldsm4(uint32_t* r, uint32_t addr) {
    asm volatile("ldmatrix.sync.aligned.m8n8.x4.shared.b16 {%0,%1,%2,%3}, [%4];"
                 : "=r"(r[0]), "=r"(r[1]), "=r"(r[2]), "=r"(r[3]) : "r"(addr));
}

__device__ __forceinline__ void mma16(float* c, const uint32_t* a, uint32_t b0, uint32_t b1) {
    asm volatile(
        "mma.sync.aligned.m16n8k16.row.col.f32.f16.f16.f32 "
        "{%0,%1,%2,%3}, {%4,%5,%6,%7}, {%8,%9}, {%0,%1,%2,%3};"
        : "+f"(c[0]), "+f"(c[1]), "+f"(c[2]), "+f"(c[3])
        : "r"(a[0]), "r"(a[1]), "r"(a[2]), "r"(a[3]), "r"(b0), "r"(b1));
}

// ---------------- preprocess kernels ----------------
__global__ void round_fp16_kernel(const float* __restrict__ K) {
    size_t i = (size_t)blockIdx.x * blockDim.x + threadIdx.x;
    if (i < (size_t)F_SZ * L_SZ) {
        g_Khf[i] = __float2half_rn(K[i]);
    }
}

__global__ void zero_out_kernel(float4* __restrict__ out) {
    out[blockIdx.x * 256 + threadIdx.x] = make_float4(0.f, 0.f, 0.f, 0.f);
}

// ---------------- SMEM layout (bytes from dynamic smem base) ----------------
#define OFF_BIAS    0u        /* 256*4  = 1024  */
#define OFF_W       1024u     /* 256*16 = 4096  -> 5120  */
#define OFF_XR      5120u     /* 12352 halfs = 24704 -> 29824 */
#define OFF_A       30720u    /* 2 * 8192  = 16384 -> 47104 (1024-aligned) */
#define OFF_B       47104u    /* 2 * 32768 = 65536 -> 112640 (1024-aligned) */
#define A_STRIDE    8192u
#define B_STRIDE    32768u
#define SMEM_TOTAL  112640u

// ---------------- main fused kernel (2 CTAs/SM, N-split, KC=64) ----------------
__global__ void __launch_bounds__(NTHREADS, 2)
conv_fused_kernel(const int* __restrict__ example,
                  const float* __restrict__ bias,
                  const float* __restrict__ dense_w,
                  const float* __restrict__ dense_b,
                  float* __restrict__ out) {
    extern __shared__ char smem[];
    const uint32_t smem_base = smem_u32(smem);
    const int tid = threadIdx.x;
    const int wid = tid >> 5;
    const int lane = tid & 31;
    const int wm = wid >> 2;       // 0..1 (M: 32 rows per warp)
    const int wn = wid & 3;        // 0..3 (N: 64 filters per warp, of this CTA's 256)

    // grid: 192 tiles x 8 batches x 2 filter-halves; LPT (heavy tiles first)
    const int bx = (int)blockIdx.x;
    const int i_tile = (N_TILES - 1) - (bx >> 4);
    const int b = (bx >> 1) & 7;
    const int nb = bx & 1;
    const int T0 = i_tile * M_TILE;
    const int C = i_tile + 1;      // 64-wide j-chunks (j <= T0+63)
    const int fbase = nb * N_CTA;

    // ---- stage bias, dense_w (this CTA's 256 filters), reversed-fp16 x ----
    {
        float* bs = (float*)(smem + OFF_BIAS);
        for (int f = tid; f < N_CTA; f += NTHREADS) bs[f] = bias[fbase + f];
        float4* ws = (float4*)(smem + OFF_W);
        const float4* wg = (const float4*)dense_w;
        for (int f = tid; f < N_CTA; f += NTHREADS) ws[f] = wg[fbase + f];
        // xr[a] = fp16(x[T0+63-a]) for a<=T0+63, else 0  (a in [0, T0+127))
        __half* xr = (__half*)(smem + OFF_XR);
        const int* ex = example + (size_t)b * L_SZ;
        const int atop = T0 + 127;
        for (int a = tid; a < atop; a += NTHREADS) {
            int xi = T0 + 63 - a;
            float v = (xi >= 0) ? ((float)ex[xi] * 0.5f - 1.0f) : 0.0f;
            xr[a] = __float2half_rn(v);
        }
    }
    __syncthreads();

    const __half* xr = (const __half*)(smem + OFF_XR);

    // ---- ldmatrix lane offsets (SW128, XOR-composed; col bits < 128, no carry) ----
    // A frag mt=0: row = wm*32 + (lane&15); static col = ((lane>>4)<<4). Boot mt=1: +16 rows.
    uint32_t a_pre, a_boot;
    {
        uint32_t rowbase = (uint32_t)(wm * 32 + (lane & 15)) * 128u;
        uint32_t swz = (rowbase >> 3) & 0x70u;
        uint32_t col = (uint32_t)((lane >> 4) << 4);
        a_pre = rowbase + (col ^ swz);
        uint32_t rb2 = rowbase + 16u * 128u;
        uint32_t swz2 = (rb2 >> 3) & 0x70u;
        a_boot = rb2 + (col ^ swz2);
    }
    // B frag (n16 group g): n = wn*64 + g*16 + (lane&7) + (((lane>>4)&1)<<3);
    // static col byte = ((lane>>3)&1)<<4
    uint32_t b_pre[4];
    #pragma unroll
    for (int g = 0; g < 4; g++) {
        uint32_t n = (uint32_t)(wn * 64 + g * 16 + (lane & 7) + (((lane >> 4) & 1) << 3));
        uint32_t rowbase = n * 128u;
        uint32_t swz = (rowbase >> 3) & 0x70u;
        uint32_t col = (uint32_t)(((lane >> 3) & 1) << 4);
        b_pre[g] = rowbase + (col ^ swz);
    }

    // A build: thread t -> row = t>>2 (0..63), k-cols (t&3)*16 .. +15 (32B fp16)
    const int arow = tid >> 2;
    const int acol = (tid & 3) * 16;

    // Hoisted B cp.async addressing: 8 quanta of 16B per thread per chunk
    uint32_t b_srcoff[8];   // byte offset into g_Khf (add J*2 per chunk)
    uint32_t b_dsw[8];      // swizzled SMEM offset within a B stage
    #pragma unroll
    for (int q = 0; q < 8; q++) {
        int linear = tid + q * NTHREADS;   // 0..2047
        int f = linear >> 3;               // 0..255 local filter
        int ch = linear & 7;
        b_srcoff[q] = (uint32_t)((fbase + f) * (L_SZ * 2) + ch * 16);
        b_dsw[q] = SWZ128((uint32_t)(f * 128 + ch * 16));
    }
    const char* kbase = (const char*)g_Khf;

    float acc[2][8][4];
    #pragma unroll
    for (int mt = 0; mt < 2; mt++)
        #pragma unroll
        for (int nt = 0; nt < 8; nt++)
            #pragma unroll
            for (int k = 0; k < 4; k++) acc[mt][nt][k] = 0.0f;

    // ---- chunk builder ----
    auto build_chunk = [&](int j, int st) {
        const int J = j * KC;
        #pragma unroll
        for (int q = 0; q < 8; q++) {
            const char* src = kbase + b_srcoff[q] + (uint32_t)(J * 2);
            uint32_t dst = smem_base + OFF_B + (uint32_t)st * B_STRIDE + b_dsw[q];
            CP16(dst, src);
        }
        // A[r,k] = x[T0+r-J-k] = xr[J+63-r+k] (contiguous ascending in k)
        {
            char* Ab = smem + OFF_A + st * A_STRIDE;
            int a0 = J + 63 - arow + acol;
            uint4 v0, v1;
            {
                __half2 p0 = __halves2half2(xr[a0],      xr[a0 + 1]);
                __half2 p1 = __halves2half2(xr[a0 + 2],  xr[a0 + 3]);
                __half2 p2 = __halves2half2(xr[a0 + 4],  xr[a0 + 5]);
                __half2 p3 = __halves2half2(xr[a0 + 6],  xr[a0 + 7]);
                v0.x = *(const uint32_t*)&p0;
                v0.y = *(const uint32_t*)&p1;
                v0.z = *(const uint32_t*)&p2;
                v0.w = *(const uint32_t*)&p3;
            }
            {
                __half2 p0 = __halves2half2(xr[a0 + 8],  xr[a0 + 9]);
                __half2 p1 = __halves2half2(xr[a0 + 10], xr[a0 + 11]);
                __half2 p2 = __halves2half2(xr[a0 + 12], xr[a0 + 13]);
                __half2 p3 = __halves2half2(xr[a0 + 14], xr[a0 + 15]);
                v1.x = *(const uint32_t*)&p0;
                v1.y = *(const uint32_t*)&p1;
                v1.z = *(const uint32_t*)&p2;
                v1.w = *(const uint32_t*)&p3;
            }
            uint32_t o = (uint32_t)(arow * 128 + acol * 2);
            *(uint4*)(Ab + SWZ128(o)) = v0;
            *(uint4*)(Ab + SWZ128(o + 16)) = v1;
        }
        CP_COMMIT();
    };

    // ---- prologue: chunk 0 ----
    build_chunk(0, 0);

    uint32_t prev[4];   // Toeplitz A chain: frag(mt=1, kk) == frag(mt=0, kk-1)

    // ---- mainloop: 2-stage ring, one barrier per 64-k chunk, build-after-barrier ----
    for (int c = 0; c < C; c++) {
        const int st = c & 1;
        CP_WAIT(0);                  // chunk c's group (only outstanding) done
        __syncthreads();             // stage st visible; all reads of st^1 retired
        if (c + 1 < C) build_chunk(c + 1, st ^ 1);

        const uint32_t abase = smem_base + OFF_A + (uint32_t)st * A_STRIDE;
        const uint32_t bbase = smem_base + OFF_B + (uint32_t)st * B_STRIDE;

        if (c == 0) ldsm4(prev, abase + a_boot);   // bootstrap frag(1,0)

        #pragma unroll
        for (int kk = 0; kk < 4; kk++) {           // 4 x k16 = 64 k per chunk
            const uint32_t kx = (uint32_t)(kk * 32);
            uint32_t cur[4];
            ldsm4(cur, abase + (a_pre ^ kx));      // frag(0,kk) -> also frag(1,kk+1)
            uint32_t bfr[4][4];
            #pragma unroll
            for (int g = 0; g < 4; g++)
                ldsm4(bfr[g], bbase + (b_pre[g] ^ kx));
            #pragma unroll
            for (int nt = 0; nt < 8; nt++) {
                mma16(acc[0][nt], cur,  bfr[nt >> 1][(nt & 1) * 2],
                      bfr[nt >> 1][(nt & 1) * 2 + 1]);
                mma16(acc[1][nt], prev, bfr[nt >> 1][(nt & 1) * 2],
                      bfr[nt >> 1][(nt & 1) * 2 + 1]);
            }
            #pragma unroll
            for (int r = 0; r < 4; r++) prev[r] = cur[r];
        }
    }
    __syncthreads();   // all stage reads done before epilogue reuses OFF_A

    // ---- fused epilogue: bias + ReLU + dense[256x4] partial, atomicAdd ----
    {
        const float* bs = (const float*)(smem + OFF_BIAS);
        const float4* ws = (const float4*)(smem + OFF_W);
        const int g = lane >> 2;
        const int cp = lane & 3;

        // rows wm*32 + mt*16 + h*8 + g
        float4 part[2][2];
        #pragma unroll
        for (int mt = 0; mt < 2; mt++)
            #pragma unroll
            for (int h = 0; h < 2; h++) {
                float4 p = make_float4(0.f, 0.f, 0.f, 0.f);
                #pragma unroll
                for (int nt = 0; nt < 8; nt++) {
                    int f0 = wn * 64 + nt * 8 + 2 * cp;    // local filter
                    float v0 = fmaxf(acc[mt][nt][h * 2 + 0] + bs[f0], 0.0f);
                    float v1 = fmaxf(acc[mt][nt][h * 2 + 1] + bs[f0 + 1], 0.0f);
                    float4 w0 = ws[f0];
                    float4 w1 = ws[f0 + 1];
                    p.x += v0 * w0.x + v1 * w1.x;
                    p.y += v0 * w0.y + v1 * w1.y;
                    p.z += v0 * w0.z + v1 * w1.z;
                    p.w += v0 * w0.w + v1 * w1.w;
                }
                part[mt][h] = p;
            }
        #pragma unroll
        for (int mt = 0; mt < 2; mt++)
            #pragma unroll
            for (int h = 0; h < 2; h++) {
                #pragma unroll
                for (int d = 1; d < 4; d <<= 1) {
                    part[mt][h].x += __shfl_xor_sync(0xFFFFFFFF, part[mt][h].x, d);
                    part[mt][h].y += __shfl_xor_sync(0xFFFFFFFF, part[mt][h].y, d);
                    part[mt][h].z += __shfl_xor_sync(0xFFFFFFFF, part[mt][h].z, d);
                    part[mt][h].w += __shfl_xor_sync(0xFFFFFFFF, part[mt][h].w, d);
                }
            }
        float4* P = (float4*)(smem + OFF_A);   // [64 rows][4 wn] = 4KB scratch
        if (cp == 0) {
            #pragma unroll
            for (int mt = 0; mt < 2; mt++)
                #pragma unroll
                for (int h = 0; h < 2; h++) {
                    int row = wm * 32 + mt * 16 + h * 8 + g;
                    P[row * 4 + wn] = part[mt][h];
                }
        }
        __syncthreads();

        if (tid < M_TILE) {
            float4 o = make_float4(0.f, 0.f, 0.f, 0.f);
            #pragma unroll
            for (int w = 0; w < 4; w++) {
                float4 p = P[tid * 4 + w];
                o.x += p.x; o.y += p.y; o.z += p.z; o.w += p.w;
            }
            if (nb == 0) {
                float4 db = *(const float4*)dense_b;
                o.x += db.x; o.y += db.y; o.z += db.z; o.w += db.w;
            }
            float* dst = out + ((size_t)b * L_SZ + T0 + tid) * 4;
            atomicAdd(dst + 0, o.x);
            atomicAdd(dst + 1, o.y);
            atomicAdd(dst + 2, o.z);
            atomicAdd(dst + 3, o.w);
        }
    }
}

extern "C" void kernel_launch(void* const* d_in, const int* in_sizes, int n_in,
                              void* d_out, int out_size) {
    const int*   example = (const int*)d_in[0];
    const float* kern    = (const float*)d_in[1];
    const float* bias    = (const float*)d_in[2];
    const float* dense_w = (const float*)d_in[3];
    const float* dense_b = (const float*)d_in[4];
    float* out = (float*)d_out;

    cudaFuncSetAttribute(conv_fused_kernel,
                         cudaFuncAttributeMaxDynamicSharedMemorySize, SMEM_TOTAL);

    // 1) zero the output (filter-split CTAs accumulate via atomicAdd)
    zero_out_kernel<<<384, 256>>>((float4*)out);
    // 2) round conv weights to fp16-RN into static scratch
    {
        size_t n = (size_t)F_SZ * L_SZ;
        int blocks = (int)((n + 255) / 256);
        round_fp16_kernel<<<blocks, 256>>>(kern);
    }
    // 3) fused Toeplitz-GEMM + bias + ReLU + dense, N-split, 2 CTAs/SM, KC=64
    conv_fused_kernel<<<N_TILES * B_SZ * 2, NTHREADS, SMEM_TOTAL>>>(
        example, bias, dense_w, dense_b, out);
}

// round 17
// speedup vs baseline: 1.2725x; 1.0323x over previous
#include <cuda_runtime.h>
#include <cuda_fp16.h>
#include <cstdint>
#include <cstddef>

#define B_SZ 8
#define L_SZ 12288
#define F_SZ 512
#define NTHREADS 256
#define M_TILE 64
#define N_CTA 256          /* filters per CTA (split across 2 CTAs) */
#define N_TILES 192        /* L / M_TILE */
#define KC 64              /* k elements per chunk (128B rows fp16, SW128) */

// fp16-rounded copy of the conv kernel weights (12.5MB static device scratch)
__device__ __half g_Khf[(size_t)F_SZ * L_SZ];

// ---------------- helpers ----------------
__device__ __forceinline__ uint32_t smem_u32(const void* p) {
    uint32_t a;
    asm("{ .reg .u64 t; cvta.to.shared.u64 t, %1; cvt.u32.u64 %0, t; }" : "=r"(a) : "l"(p));
    return a;
}
#define SWZ128(o) ((o) ^ (((o) >> 3) & 0x70))

#define CP16(dst, src) \
    asm volatile("cp.async.cg.shared.global [%0], [%1], 16;" :: "r"(dst), "l"(src))
#define CP_COMMIT() asm volatile("cp.async.commit_group;" ::: "memory")
#define CP_WAIT(N) asm volatile("cp.async.wait_group %0;" :: "n"(N) : "memory")

__device__ __forceinline__ void ldsm4(uint32_t* r, uint32_t addr) {
    asm volatile("ldmatrix.sync.aligned.m8n8.x4.shared.b16 {%0,%1,%2,%3}, [%4];"
                 : "=r"(r[0]), "=r"(r[1]), "=r"(r[2]), "=r"(r[3]) : "r"(addr));
}

__device__ __forceinline__ void mma16(float* c, const uint32_t* a, uint32_t b0, uint32_t b1) {
    asm volatile(
        "mma.sync.aligned.m16n8k16.row.col.f32.f16.f16.f32 "
        "{%0,%1,%2,%3}, {%4,%5,%6,%7}, {%8,%9}, {%0,%1,%2,%3};"
        : "+f"(c[0]), "+f"(c[1]), "+f"(c[2]), "+f"(c[3])
        : "r"(a[0]), "r"(a[1]), "r"(a[2]), "r"(a[3]), "r"(b0), "r"(b1));
}

// ---------------- preprocess: round K to fp16 + zero output (one launch) ----------------
__global__ void init_kernel(const float* __restrict__ K, float4* __restrict__ out) {
    size_t i = (size_t)blockIdx.x * blockDim.x + threadIdx.x;
    if (i < (size_t)F_SZ * L_SZ) {
        g_Khf[i] = __float2half_rn(K[i]);
    }
    if (i < (size_t)B_SZ * L_SZ) {           // 98304 float4 = output
        out[i] = make_float4(0.f, 0.f, 0.f, 0.f);
    }
}

// ---------------- SMEM layout (bytes from dynamic smem base) ----------------
#define OFF_BIAS    0u        /* 256*4  = 1024  */
#define OFF_W       1024u     /* 256*16 = 4096  -> 5120  */
#define OFF_XR      5120u     /* 12352 halfs = 24704 -> 29824 */
#define OFF_A       30720u    /* 2 * 8192  = 16384 -> 47104 (1024-aligned) */
#define OFF_B       47104u    /* 2 * 32768 = 65536 -> 112640 (1024-aligned) */
#define A_STRIDE    8192u
#define B_STRIDE    32768u
#define SMEM_TOTAL  112640u

// ---------------- main fused kernel (2 CTAs/SM, N-split, KC=64) ----------------
__global__ void __launch_bounds__(NTHREADS, 2)
conv_fused_kernel(const int* __restrict__ example,
                  const float* __restrict__ bias,
                  const float* __restrict__ dense_w,
                  const float* __restrict__ dense_b,
                  float* __restrict__ out) {
    extern __shared__ char smem[];
    const uint32_t smem_base = smem_u32(smem);
    const int tid = threadIdx.x;
    const int wid = tid >> 5;
    const int lane = tid & 31;
    const int wm = wid >> 2;       // 0..1 (M: 32 rows per warp)
    const int wn = wid & 3;        // 0..3 (N: 64 filters per warp, of this CTA's 256)

    // grid: 192 tiles x 8 batches x 2 filter-halves; LPT (heavy tiles first)
    const int bx = (int)blockIdx.x;
    const int i_tile = (N_TILES - 1) - (bx >> 4);
    const int b = (bx >> 1) & 7;
    const int nb = bx & 1;
    const int T0 = i_tile * M_TILE;
    const int C = i_tile + 1;      // 64-wide j-chunks (j <= T0+63)
    const int fbase = nb * N_CTA;

    // ---- stage bias, dense_w (this CTA's 256 filters), reversed-fp16 x ----
    {
        float* bs = (float*)(smem + OFF_BIAS);
        for (int f = tid; f < N_CTA; f += NTHREADS) bs[f] = bias[fbase + f];
        float4* ws = (float4*)(smem + OFF_W);
        const float4* wg = (const float4*)dense_w;
        for (int f = tid; f < N_CTA; f += NTHREADS) ws[f] = wg[fbase + f];
        // xr[a] = fp16(x[T0+63-a]) for a<=T0+63, else 0  (a in [0, T0+127))
        __half* xr = (__half*)(smem + OFF_XR);
        const int* ex = example + (size_t)b * L_SZ;
        const int atop = T0 + 127;
        for (int a = tid; a < atop; a += NTHREADS) {
            int xi = T0 + 63 - a;
            float v = (xi >= 0) ? ((float)ex[xi] * 0.5f - 1.0f) : 0.0f;
            xr[a] = __float2half_rn(v);
        }
    }
    __syncthreads();

    const __half* xr = (const __half*)(smem + OFF_XR);

    // ---- ldmatrix lane offsets (SW128, XOR-composed; col bits < 128, no carry) ----
    // A frag mt=0: row = wm*32 + (lane&15); static col = ((lane>>4)<<4). Boot mt=1: +16 rows.
    uint32_t a_pre, a_boot;
    {
        uint32_t rowbase = (uint32_t)(wm * 32 + (lane & 15)) * 128u;
        uint32_t swz = (rowbase >> 3) & 0x70u;
        uint32_t col = (uint32_t)((lane >> 4) << 4);
        a_pre = rowbase + (col ^ swz);
        uint32_t rb2 = rowbase + 16u * 128u;
        uint32_t swz2 = (rb2 >> 3) & 0x70u;
        a_boot = rb2 + (col ^ swz2);
    }
    // B frag (n16 group g): n = wn*64 + g*16 + (lane&7) + (((lane>>4)&1)<<3);
    // static col byte = ((lane>>3)&1)<<4
    uint32_t b_pre[4];
    #pragma unroll
    for (int g = 0; g < 4; g++) {
        uint32_t n = (uint32_t)(wn * 64 + g * 16 + (lane & 7) + (((lane >> 4) & 1) << 3));
        uint32_t rowbase = n * 128u;
        uint32_t swz = (rowbase >> 3) & 0x70u;
        uint32_t col = (uint32_t)(((lane >> 3) & 1) << 4);
        b_pre[g] = rowbase + (col ^ swz);
    }

    // A build: thread t -> row = t>>2 (0..63), k-cols (t&3)*16 .. +15 (32B fp16)
    const int arow = tid >> 2;
    const int acol = (tid & 3) * 16;

    // Hoisted B cp.async addressing: 8 quanta of 16B per thread per chunk
    uint32_t b_srcoff[8];   // byte offset into g_Khf (add J*2 per chunk)
    uint32_t b_dsw[8];      // swizzled SMEM offset within a B stage
    #pragma unroll
    for (int q = 0; q < 8; q++) {
        int linear = tid + q * NTHREADS;   // 0..2047
        int f = linear >> 3;               // 0..255 local filter
        int ch = linear & 7;
        b_srcoff[q] = (uint32_t)((fbase + f) * (L_SZ * 2) + ch * 16);
        b_dsw[q] = SWZ128((uint32_t)(f * 128 + ch * 16));
    }
    const char* kbase = (const char*)g_Khf;

    float acc[2][8][4];
    #pragma unroll
    for (int mt = 0; mt < 2; mt++)
        #pragma unroll
        for (int nt = 0; nt < 8; nt++)
            #pragma unroll
            for (int k = 0; k < 4; k++) acc[mt][nt][k] = 0.0f;

    // ---- split builders: B via cp.async (issue early), A via STS (issue late) ----
    auto build_B = [&](int j, int st) {
        const int J = j * KC;
        #pragma unroll
        for (int q = 0; q < 8; q++) {
            const char* src = kbase + b_srcoff[q] + (uint32_t)(J * 2);
            uint32_t dst = smem_base + OFF_B + (uint32_t)st * B_STRIDE + b_dsw[q];
            CP16(dst, src);
        }
        CP_COMMIT();
    };
    auto build_A = [&](int j, int st) {
        const int J = j * KC;
        // A[r,k] = x[T0+r-J-k] = xr[J+63-r+k] (contiguous ascending in k)
        char* Ab = smem + OFF_A + st * A_STRIDE;
        int a0 = J + 63 - arow + acol;
        uint4 v0, v1;
        {
            __half2 p0 = __halves2half2(xr[a0],      xr[a0 + 1]);
            __half2 p1 = __halves2half2(xr[a0 + 2],  xr[a0 + 3]);
            __half2 p2 = __halves2half2(xr[a0 + 4],  xr[a0 + 5]);
            __half2 p3 = __halves2half2(xr[a0 + 6],  xr[a0 + 7]);
            v0.x = *(const uint32_t*)&p0;
            v0.y = *(const uint32_t*)&p1;
            v0.z = *(const uint32_t*)&p2;
            v0.w = *(const uint32_t*)&p3;
        }
        {
            __half2 p0 = __halves2half2(xr[a0 + 8],  xr[a0 + 9]);
            __half2 p1 = __halves2half2(xr[a0 + 10], xr[a0 + 11]);
            __half2 p2 = __halves2half2(xr[a0 + 12], xr[a0 + 13]);
            __half2 p3 = __halves2half2(xr[a0 + 14], xr[a0 + 15]);
            v1.x = *(const uint32_t*)&p0;
            v1.y = *(const uint32_t*)&p1;
            v1.z = *(const uint32_t*)&p2;
            v1.w = *(const uint32_t*)&p3;
        }
        uint32_t o = (uint32_t)(arow * 128 + acol * 2);
        *(uint4*)(Ab + SWZ128(o)) = v0;
        *(uint4*)(Ab + SWZ128(o + 16)) = v1;
    };

    // ---- prologue: chunk 0 ----
    build_B(0, 0);
    build_A(0, 0);

    uint32_t prev[4];   // Toeplitz A chain: frag(mt=1, kk) == frag(mt=0, kk-1)

    // ---- mainloop: 2-stage ring, one barrier per 64-k chunk ----
    // Order inside chunk c: wait/barrier -> cp.async B(c+1) -> MMAs(c) -> A-build(c+1).
    // A-build(c+1) targets stage st^1, free since the barrier (reads retired at c-1).
    for (int c = 0; c < C; c++) {
        const int st = c & 1;
        CP_WAIT(0);                  // chunk c's B group (only outstanding) done
        __syncthreads();             // stage st visible; all reads of st^1 retired
        if (c + 1 < C) build_B(c + 1, st ^ 1);   // async engine fills during MMAs

        const uint32_t abase = smem_base + OFF_A + (uint32_t)st * A_STRIDE;
        const uint32_t bbase = smem_base + OFF_B + (uint32_t)st * B_STRIDE;

        if (c == 0) ldsm4(prev, abase + a_boot);   // bootstrap frag(1,0)

        #pragma unroll
        for (int kk = 0; kk < 4; kk++) {           // 4 x k16 = 64 k per chunk
            const uint32_t kx = (uint32_t)(kk * 32);
            uint32_t cur[4];
            ldsm4(cur, abase + (a_pre ^ kx));      // frag(0,kk) -> also frag(1,kk+1)
            uint32_t bfr[4][4];
            #pragma unroll
            for (int g = 0; g < 4; g++)
                ldsm4(bfr[g], bbase + (b_pre[g] ^ kx));
            #pragma unroll
            for (int nt = 0; nt < 8; nt++) {
                mma16(acc[0][nt], cur,  bfr[nt >> 1][(nt & 1) * 2],
                      bfr[nt >> 1][(nt & 1) * 2 + 1]);
                mma16(acc[1][nt], prev, bfr[nt >> 1][(nt & 1) * 2],
                      bfr[nt >> 1][(nt & 1) * 2 + 1]);
            }
            #pragma unroll
            for (int r = 0; r < 4; r++) prev[r] = cur[r];
        }

        if (c + 1 < C) build_A(c + 1, st ^ 1);     // off the MMA critical path
    }
    __syncthreads();   // all stage reads done before epilogue reuses OFF_A

    // ---- fused epilogue: bias + ReLU + dense[256x4] partial, atomicAdd ----
    {
        const float* bs = (const float*)(smem + OFF_BIAS);
        const float4* ws = (const float4*)(smem + OFF_W);
        const int g = lane >> 2;
        const int cp = lane & 3;

        // rows wm*32 + mt*16 + h*8 + g
        float4 part[2][2];
        #pragma unroll
        for (int mt = 0; mt < 2; mt++)
            #pragma unroll
            for (int h = 0; h < 2; h++) {
                float4 p = make_float4(0.f, 0.f, 0.f, 0.f);
                #pragma unroll
                for (int nt = 0; nt < 8; nt++) {
                    int f0 = wn * 64 + nt * 8 + 2 * cp;    // local filter
                    float v0 = fmaxf(acc[mt][nt][h * 2 + 0] + bs[f0], 0.0f);
                    float v1 = fmaxf(acc[mt][nt][h * 2 + 1] + bs[f0 + 1], 0.0f);
                    float4 w0 = ws[f0];
                    float4 w1 = ws[f0 + 1];
                    p.x += v0 * w0.x + v1 * w1.x;
                    p.y += v0 * w0.y + v1 * w1.y;
                    p.z += v0 * w0.z + v1 * w1.z;
                    p.w += v0 * w0.w + v1 * w1.w;
                }
                part[mt][h] = p;
            }
        #pragma unroll
        for (int mt = 0; mt < 2; mt++)
            #pragma unroll
            for (int h = 0; h < 2; h++) {
                #pragma unroll
                for (int d = 1; d < 4; d <<= 1) {
                    part[mt][h].x += __shfl_xor_sync(0xFFFFFFFF, part[mt][h].x, d);
                    part[mt][h].y += __shfl_xor_sync(0xFFFFFFFF, part[mt][h].y, d);
                    part[mt][h].z += __shfl_xor_sync(0xFFFFFFFF, part[mt][h].z, d);
                    part[mt][h].w += __shfl_xor_sync(0xFFFFFFFF, part[mt][h].w, d);
                }
            }
        float4* P = (float4*)(smem + OFF_A);   // [64 rows][4 wn] = 4KB scratch
        if (cp == 0) {
            #pragma unroll
            for (int mt = 0; mt < 2; mt++)
                #pragma unroll
                for (int h = 0; h < 2; h++) {
                    int row = wm * 32 + mt * 16 + h * 8 + g;
                    P[row * 4 + wn] = part[mt][h];
                }
        }
        __syncthreads();

        if (tid < M_TILE) {
            float4 o = make_float4(0.f, 0.f, 0.f, 0.f);
            #pragma unroll
            for (int w = 0; w < 4; w++) {
                float4 p = P[tid * 4 + w];
                o.x += p.x; o.y += p.y; o.z += p.z; o.w += p.w;
            }
            if (nb == 0) {
                float4 db = *(const float4*)dense_b;
                o.x += db.x; o.y += db.y; o.z += db.z; o.w += db.w;
            }
            float* dst = out + ((size_t)b * L_SZ + T0 + tid) * 4;
            atomicAdd(dst + 0, o.x);
            atomicAdd(dst + 1, o.y);
            atomicAdd(dst + 2, o.z);
            atomicAdd(dst + 3, o.w);
        }
    }
}

extern "C" void kernel_launch(void* const* d_in, const int* in_sizes, int n_in,
                              void* d_out, int out_size) {
    const int*   example = (const int*)d_in[0];
    const float* kern    = (const float*)d_in[1];
    const float* bias    = (const float*)d_in[2];
    const float* dense_w = (const float*)d_in[3];
    const float* dense_b = (const float*)d_in[4];
    float* out = (float*)d_out;

    cudaFuncSetAttribute(conv_fused_kernel,
                         cudaFuncAttributeMaxDynamicSharedMemorySize, SMEM_TOTAL);

    // 1) round conv weights to fp16-RN + zero output (single launch)
    {
        size_t n = (size_t)F_SZ * L_SZ;
        int blocks = (int)((n + 255) / 256);
        init_kernel<<<blocks, 256>>>(kern, (float4*)out);
    }
    // 2) fused Toeplitz-GEMM + bias + ReLU + dense, N-split, 2 CTAs/SM, KC=64
    conv_fused_kernel<<<N_TILES * B_SZ * 2, NTHREADS, SMEM_TOTAL>>>(
        example, bias, dense_w, dense_b, out);
}